// round 10
// baseline (speedup 1.0000x reference)
#include <cuda_runtime.h>
#include <cstdint>

// Problem constants
#define B_DIM   16
#define L_DIM   160000
#define N_WT    10
#define WT_LEN  512
#define FIR_TAPS 31
#define WT_TOT  (N_WT * WT_LEN)

// Blocked-scan parameters (XLA ReduceWindowRewriter, base_length = 16)
#define NS1 10000
#define NS2 625
#define NS3 40
#define NS4 3

// k_main tiling: 640 threads x 10 samples = 6400-sample tiles, 25 tiles/row
// grid = 25*16 = 400 blocks <= 444 concurrent (3/SM) -> single wave
#define TPB   640
#define SAMP  10
#define TILE  (TPB * SAMP)          // 6400

// k_s1 tiling: 80 tiles/row, 2000 pitch values -> 125 S1 groups per tile
#define S1_TILES 80
#define S1_PITCH 2000
#define S1_GRP   125

// k_main dynamic smem: pair table + staged increments
#define SP_BYTES   (WT_TOT * 8)     // 40960
#define SINC_BYTES (TILE * 4)       // 25600
#define SMEM_MAIN  (SP_BYTES + SINC_BYTES)   // 66560

__device__ __forceinline__ float KF() { return (float)(512.0 / 16000.0); }

// Scratch
__device__ float  g_S1[B_DIM][NS1];   // 16-block sums of increments
__device__ float  g_O1[B_DIM][NS1];   // composed inclusive scan at level 1
__device__ float  g_wt[WT_TOT];       // FIR-filtered wavetables
__device__ float4 g_wtp4[WT_TOT / 2]; // packed (lo,hi) pairs, 2 per float4

// ---------------------------------------------------------------------------
// k_s1: blocks x<80: S1 via coalesced pad-17 smem staging, strict sequential
// rn 16-sums (verified chain).  Block x==80,y==0: FIR + pair table, reading
// the 20KB wavetable through L1 (no smem staging -> small footprint for ALL
// blocks: ~8.6 KB -> 8 blocks/SM).
// ---------------------------------------------------------------------------
__global__ void k_s1(const float* __restrict__ pitch,
                     const float* __restrict__ wtab,
                     const float* __restrict__ firh)
{
    __shared__ float st[S1_GRP * 17];       // 8500 B
    __shared__ float sh[FIR_TAPS];          // 124 B

    if (blockIdx.x == S1_TILES) {           // FIR + pair block
        if (blockIdx.y != 0) return;
        if (threadIdx.x < FIR_TAPS) sh[threadIdx.x] = firh[threadIdx.x];
        __syncthreads();
        // FIR: wavetable reads go through L1 (20KB, fully resident)
        for (int idx = threadIdx.x; idx < WT_TOT; idx += blockDim.x) {
            int base_w = idx & ~511;
            int i = idx & 511;
            float s = 0.0f;
            #pragma unroll
            for (int k = 0; k < FIR_TAPS; k++) {
                int j = (i + k - 15 + WT_LEN) & 511;
                s = __fadd_rn(s, __fmul_rn(__ldg(wtab + (base_w | j)), sh[k]));
            }
            g_wt[idx] = s;
        }
        __syncthreads();   // orders g_wt writes vs reads within this block
        // pack (value, next) pairs, two per float4
        for (int p = threadIdx.x; p < WT_TOT / 2; p += blockDim.x) {
            int i0 = 2 * p, i1 = 2 * p + 1;
            int bw0 = i0 & ~511, bw1 = i1 & ~511;
            float4 v;
            v.x = g_wt[i0]; v.y = g_wt[bw0 | ((i0 + 1) & 511)];
            v.z = g_wt[i1]; v.w = g_wt[bw1 | ((i1 + 1) & 511)];
            g_wtp4[p] = v;
        }
        return;
    }

    const int b   = blockIdx.y;
    const int tid = threadIdx.x;
    const float k = KF();

    // coalesced load of 2000 pitch values, pre-multiplied, pad-17 scatter
    const float* P = pitch + b * L_DIM + blockIdx.x * S1_PITCH;
    for (int i = tid; i < S1_PITCH; i += 256) {
        float v = __fmul_rn(k, P[i]);
        st[(i >> 4) * 17 + (i & 15)] = v;
    }
    __syncthreads();

    // S1: strict sequential sum of 16 staged increments (conflict-free LDS)
    if (tid < S1_GRP) {
        const float* row = st + tid * 17;
        float acc = 0.0f;
        #pragma unroll
        for (int e = 0; e < 16; e++)
            acc = __fadd_rn(acc, row[e]);
        g_S1[b][blockIdx.x * S1_GRP + tid] = acc;
    }
}

// ---------------------------------------------------------------------------
// k_scan: one block per batch row.  Everything after S1 (verified chain):
//   stage S1 (pad-17) -> S2 -> S3 -> S4 -> O4 -> O3 -> O2 -> O1 -> writeout.
// ---------------------------------------------------------------------------
__global__ void k_scan()
{
    __shared__ float s1p[NS2 * 17];
    __shared__ float sS2[NS2];
    __shared__ float sS3[NS3];
    __shared__ float sS4[NS4];
    __shared__ float sO4[NS4];
    __shared__ float sO3[NS3];
    __shared__ float sO2[NS2];

    const int b   = blockIdx.x;
    const int tid = threadIdx.x;

    for (int i = tid; i < NS1; i += 1024)
        s1p[(i >> 4) * 17 + (i & 15)] = g_S1[b][i];
    __syncthreads();

    if (tid < NS2) {
        const float* row = s1p + tid * 17;
        float acc = 0.0f;
        #pragma unroll
        for (int e = 0; e < 16; e++)
            acc = __fadd_rn(acc, row[e]);
        sS2[tid] = acc;
    }
    __syncthreads();

    if (tid < NS3) {
        float acc = 0.0f;
        for (int e = 0; e < 16; e++) {
            int idx = (tid << 4) + e;
            if (idx < NS2) acc = __fadd_rn(acc, sS2[idx]);
        }
        sS3[tid] = acc;
    }
    __syncthreads();

    if (tid < NS4) {
        float acc = 0.0f;
        for (int e = 0; e < 16; e++) {
            int idx = (tid << 4) + e;
            if (idx < NS3) acc = __fadd_rn(acc, sS3[idx]);
        }
        sS4[tid] = acc;
    }
    __syncthreads();

    if (tid == 0) {
        float acc = 0.0f;
        for (int m = 0; m < NS4; m++) {
            acc = __fadd_rn(acc, sS4[m]);
            sO4[m] = acc;
        }
    }
    __syncthreads();

    if (tid < NS3) {
        int blk = tid >> 4;
        float acc = 0.0f;
        for (int m = (blk << 4); m <= tid; m++)
            acc = __fadd_rn(acc, sS3[m]);
        sO3[tid] = blk ? __fadd_rn(acc, sO4[blk - 1]) : acc;
    }
    __syncthreads();

    if (tid < NS2) {
        int blk = tid >> 4;
        float acc = 0.0f;
        for (int m = (blk << 4); m <= tid; m++)
            acc = __fadd_rn(acc, sS2[m]);
        sO2[tid] = blk ? __fadd_rn(acc, sO3[blk - 1]) : acc;
    }
    __syncthreads();

    if (tid < NS2) {
        float* row = s1p + tid * 17;
        float prev = (tid > 0) ? sO2[tid - 1] : 0.0f;
        float acc = 0.0f;
        #pragma unroll
        for (int e = 0; e < 16; e++) {
            acc = __fadd_rn(acc, row[e]);
            row[e] = (tid > 0) ? __fadd_rn(acc, prev) : acc;
        }
    }
    __syncthreads();

    for (int i = tid; i < NS1; i += 1024)
        g_O1[b][i] = s1p[(i >> 4) * 17 + (i & 15)];
}

// ---------------------------------------------------------------------------
// k_main: 6400-sample tiles (10 samples/thread); single-wave grid (400
// blocks, 3/SM).  Per-sample arithmetic is the EXACT R4-verified chain.
// ---------------------------------------------------------------------------
__global__ void __launch_bounds__(TPB, 3) k_main(
        const float* __restrict__ pitch,
        const float* __restrict__ env,
        const float* __restrict__ att,
        float* __restrict__ out)
{
    extern __shared__ char smem_raw[];
    float2* sp   = (float2*)smem_raw;
    float*  sinc = (float*)(smem_raw + SP_BYTES);

    const int tid = threadIdx.x;
    const int b   = blockIdx.y;
    const int base_t = blockIdx.x * TILE;
    const float k = KF();

    // pair-table fill: 4 x LDG.128 per thread
    {
        float4* sp4 = (float4*)sp;
        #pragma unroll
        for (int it = 0; it < (WT_TOT / 2) / TPB; it++)
            sp4[tid + it * TPB] = g_wtp4[tid + it * TPB];
    }

    // staged increments for the whole tile (16-groups never straddle: 6400%16==0)
    #pragma unroll
    for (int s = 0; s < SAMP; s++) {
        int m = tid + s * TPB;
        sinc[m] = __fmul_rn(k, pitch[b * L_DIM + base_t + m]);
    }
    __syncthreads();

    #pragma unroll 1
    for (int s = 0; s < SAMP; s++) {
        const int m = tid + s * TPB;
        const int t = base_t + m;

        // strict sequential prefix within the 16-group
        const int r0 = m & 15;
        const int lb = m & ~15;
        float acc = 0.0f;
        for (int e = 0; e <= r0; e++)
            acc = __fadd_rn(acc, sinc[lb + e]);
        const int j0 = t >> 4;
        float v = j0 ? __fadd_rn(acc, g_O1[b][j0 - 1]) : acc;

        // index = cumsum - rn(k * pitch_row0[t])
        float index = __fsub_rn(v, __fmul_rn(k, pitch[t]));

        // exact trunc-remainder by 512 (bitwise == fmodf) + jnp.remainder fixup
        float q = truncf(__fmul_rn(index, 0.001953125f));
        float r = __fmaf_rn(-512.0f, q, index);
        if (r < 0.0f) r = __fadd_rn(r, 512.0f);
        if (__fsub_rn(512.0f, r) < 1e-5f) r = 0.0f;

        float lof   = floorf(r);
        float alpha = __fsub_rn(r, lof);
        int   ilo   = (int)lof;

        const int basei = b * L_DIM + t;
        const float2* ap = (const float2*)(att + (size_t)basei * N_WT);
        float2 a0 = ap[0], a1 = ap[1], a2 = ap[2], a3 = ap[3], a4 = ap[4];
        float aw[N_WT] = {a0.x, a0.y, a1.x, a1.y, a2.x,
                          a2.y, a3.x, a3.y, a4.x, a4.y};

        float acc2 = 0.0f;
        #pragma unroll
        for (int w = 0; w < N_WT; w++) {
            float2 pr = sp[w * WT_LEN + ilo];
            float wave = __fadd_rn(pr.x, __fmul_rn(alpha, __fsub_rn(pr.y, pr.x)));
            acc2 = __fadd_rn(acc2, __fmul_rn(wave, aw[w]));
        }
        out[basei] = __fmul_rn(acc2, env[basei]);
    }
}

// ---------------------------------------------------------------------------
// d_in order: 0 pitch, 1 envelope, 2 attention, 3 wavetables, 4 fir_h
// ---------------------------------------------------------------------------
extern "C" void kernel_launch(void* const* d_in, const int* in_sizes, int n_in,
                              void* d_out, int out_size)
{
    const float* pitch = (const float*)d_in[0];
    const float* env   = (const float*)d_in[1];
    const float* att   = (const float*)d_in[2];
    const float* wtab  = (const float*)d_in[3];
    const float* firh  = (const float*)d_in[4];
    float* out = (float*)d_out;

    cudaFuncSetAttribute(k_main, cudaFuncAttributeMaxDynamicSharedMemorySize,
                         SMEM_MAIN);

    k_s1<<<dim3(S1_TILES + 1, B_DIM), 256>>>(pitch, wtab, firh);
    k_scan<<<B_DIM, 1024>>>();
    k_main<<<dim3(L_DIM / TILE, B_DIM), TPB, SMEM_MAIN>>>(pitch, env, att, out);
}

// round 11
// speedup vs baseline: 1.2233x; 1.2233x over previous
#include <cuda_runtime.h>
#include <cstdint>

// Problem constants
#define B_DIM   16
#define L_DIM   160000
#define N_WT    10
#define WT_LEN  512
#define FIR_TAPS 31
#define WT_TOT  (N_WT * WT_LEN)

// Blocked-scan parameters (XLA ReduceWindowRewriter, base_length = 16)
#define NS1 10000
#define NS2 625
#define NS3 40
#define NS4 3

// k_main tiling: 640 threads x 5 samples = 3200-sample tiles, 50 tiles/row
#define TPB   640
#define SAMP  5
#define TILE  (TPB * SAMP)          // 3200

// k_s1 tiling: 40 tiles/row, 4000 pitch values -> 250 S1 groups per tile
#define S1_TILES 40
#define S1_PITCH 4000
#define S1_GRP   250

// k_main dynamic smem: pair table + staged increments
#define SP_BYTES   (WT_TOT * 8)     // 40960
#define SINC_BYTES (TILE * 4)       // 12800
#define SMEM_MAIN  (SP_BYTES + SINC_BYTES)   // 53760

__device__ __forceinline__ float KF() { return (float)(512.0 / 16000.0); }

// Scratch
__device__ float  g_S1[B_DIM][NS1];   // 16-block sums of increments
__device__ float  g_O1[B_DIM][NS1];   // composed inclusive scan at level 1
__device__ float4 g_wtp4[WT_TOT / 2]; // packed (lo,hi) wavetable pairs

// ---------------------------------------------------------------------------
// k_s1: blocks x<40: S1 via coalesced pad-17 smem staging, strict sequential
// rn 16-sums (verified chain).  Blocks x in [40,50), y==0: FIR for wavetable
// row (x-40) — one row per block, smem-staged, writes packed pairs.
// ---------------------------------------------------------------------------
__global__ void k_s1(const float* __restrict__ pitch,
                     const float* __restrict__ wtab,
                     const float* __restrict__ firh)
{
    __shared__ union {
        float st[S1_GRP * 17];                  // 17000 B (S1 path)
        struct {
            float srow[WT_LEN];                 // 2048 B (FIR path)
            float sout[WT_LEN];
            float sh[FIR_TAPS];
        } fir;
    } u;

    if (blockIdx.x >= S1_TILES) {               // FIR row block
        if (blockIdx.y != 0) return;
        const int w = blockIdx.x - S1_TILES;    // wavetable row 0..9
        const int tid = threadIdx.x;

        if (tid < FIR_TAPS) u.fir.sh[tid] = firh[tid];
        #pragma unroll
        for (int it = 0; it < 2; it++)
            u.fir.srow[tid + it * 256] = wtab[w * WT_LEN + tid + it * 256];
        __syncthreads();

        // FIR: strict rn chain, ascending taps (verified bracketing)
        #pragma unroll
        for (int it = 0; it < 2; it++) {
            int i = tid + it * 256;
            float s = 0.0f;
            #pragma unroll
            for (int k = 0; k < FIR_TAPS; k++) {
                int j = (i + k - 15 + WT_LEN) & 511;
                s = __fadd_rn(s, __fmul_rn(u.fir.srow[j], u.fir.sh[k]));
            }
            u.fir.sout[i] = s;
        }
        __syncthreads();

        // pack (value, next) pairs for this row, two per float4
        // row w covers pair indices p in [256*w, 256*w + 256)
        {
            int i0 = 2 * threadIdx.x;           // 0..510 within row
            float4 v;
            v.x = u.fir.sout[i0];
            v.y = u.fir.sout[(i0 + 1) & 511];
            v.z = u.fir.sout[i0 + 1];
            v.w = u.fir.sout[(i0 + 2) & 511];
            g_wtp4[w * 256 + threadIdx.x] = v;
        }
        return;
    }

    const int b   = blockIdx.y;
    const int tid = threadIdx.x;
    const float k = KF();

    // coalesced load of 4000 pitch values, pre-multiplied, pad-17 scatter
    const float* P = pitch + b * L_DIM + blockIdx.x * S1_PITCH;
    for (int i = tid; i < S1_PITCH; i += 256) {
        float v = __fmul_rn(k, P[i]);
        u.st[(i >> 4) * 17 + (i & 15)] = v;
    }
    __syncthreads();

    // S1: strict sequential sum of 16 staged increments (conflict-free LDS)
    if (tid < S1_GRP) {
        const float* row = u.st + tid * 17;
        float acc = 0.0f;
        #pragma unroll
        for (int e = 0; e < 16; e++)
            acc = __fadd_rn(acc, row[e]);
        g_S1[b][blockIdx.x * S1_GRP + tid] = acc;
    }
}

// ---------------------------------------------------------------------------
// k_scan: one block per batch row.  Everything after S1 (verified chain):
//   stage S1 (pad-17) -> S2 -> S3 -> S4 -> O4 -> O3 -> O2 -> O1 -> writeout.
// ---------------------------------------------------------------------------
__global__ void k_scan()
{
    __shared__ float s1p[NS2 * 17];
    __shared__ float sS2[NS2];
    __shared__ float sS3[NS3];
    __shared__ float sS4[NS4];
    __shared__ float sO4[NS4];
    __shared__ float sO3[NS3];
    __shared__ float sO2[NS2];

    const int b   = blockIdx.x;
    const int tid = threadIdx.x;

    for (int i = tid; i < NS1; i += 1024)
        s1p[(i >> 4) * 17 + (i & 15)] = g_S1[b][i];
    __syncthreads();

    if (tid < NS2) {
        const float* row = s1p + tid * 17;
        float acc = 0.0f;
        #pragma unroll
        for (int e = 0; e < 16; e++)
            acc = __fadd_rn(acc, row[e]);
        sS2[tid] = acc;
    }
    __syncthreads();

    if (tid < NS3) {
        float acc = 0.0f;
        for (int e = 0; e < 16; e++) {
            int idx = (tid << 4) + e;
            if (idx < NS2) acc = __fadd_rn(acc, sS2[idx]);
        }
        sS3[tid] = acc;
    }
    __syncthreads();

    if (tid < NS4) {
        float acc = 0.0f;
        for (int e = 0; e < 16; e++) {
            int idx = (tid << 4) + e;
            if (idx < NS3) acc = __fadd_rn(acc, sS3[idx]);
        }
        sS4[tid] = acc;
    }
    __syncthreads();

    if (tid == 0) {
        float acc = 0.0f;
        for (int m = 0; m < NS4; m++) {
            acc = __fadd_rn(acc, sS4[m]);
            sO4[m] = acc;
        }
    }
    __syncthreads();

    if (tid < NS3) {
        int blk = tid >> 4;
        float acc = 0.0f;
        for (int m = (blk << 4); m <= tid; m++)
            acc = __fadd_rn(acc, sS3[m]);
        sO3[tid] = blk ? __fadd_rn(acc, sO4[blk - 1]) : acc;
    }
    __syncthreads();

    if (tid < NS2) {
        int blk = tid >> 4;
        float acc = 0.0f;
        for (int m = (blk << 4); m <= tid; m++)
            acc = __fadd_rn(acc, sS2[m]);
        sO2[tid] = blk ? __fadd_rn(acc, sO3[blk - 1]) : acc;
    }
    __syncthreads();

    if (tid < NS2) {
        float* row = s1p + tid * 17;
        float prev = (tid > 0) ? sO2[tid - 1] : 0.0f;
        float acc = 0.0f;
        #pragma unroll
        for (int e = 0; e < 16; e++) {
            acc = __fadd_rn(acc, row[e]);
            row[e] = (tid > 0) ? __fadd_rn(acc, prev) : acc;
        }
    }
    __syncthreads();

    for (int i = tid; i < NS1; i += 1024)
        g_O1[b][i] = s1p[(i >> 4) * 17 + (i & 15)];
}

// ---------------------------------------------------------------------------
// k_main: EXACT R9 version (3200-sample tiles, 5 samples/thread, float4
// pair-table fill; verified ~41us, rel_err 1.379262e-7).
// ---------------------------------------------------------------------------
__global__ void __launch_bounds__(TPB, 3) k_main(
        const float* __restrict__ pitch,
        const float* __restrict__ env,
        const float* __restrict__ att,
        float* __restrict__ out)
{
    extern __shared__ char smem_raw[];
    float2* sp   = (float2*)smem_raw;
    float*  sinc = (float*)(smem_raw + SP_BYTES);

    const int tid = threadIdx.x;
    const int b   = blockIdx.y;
    const int base_t = blockIdx.x * TILE;
    const float k = KF();

    // pair-table fill: 4 x LDG.128 per thread
    {
        float4* sp4 = (float4*)sp;
        #pragma unroll
        for (int it = 0; it < (WT_TOT / 2) / TPB; it++)
            sp4[tid + it * TPB] = g_wtp4[tid + it * TPB];
    }

    // staged increments for the whole tile (16-groups never straddle: 3200%16==0)
    #pragma unroll
    for (int s = 0; s < SAMP; s++) {
        int m = tid + s * TPB;
        sinc[m] = __fmul_rn(k, pitch[b * L_DIM + base_t + m]);
    }
    __syncthreads();

    #pragma unroll 1
    for (int s = 0; s < SAMP; s++) {
        const int m = tid + s * TPB;
        const int t = base_t + m;

        // strict sequential prefix within the 16-group
        const int r0 = m & 15;
        const int lb = m & ~15;
        float acc = 0.0f;
        for (int e = 0; e <= r0; e++)
            acc = __fadd_rn(acc, sinc[lb + e]);
        const int j0 = t >> 4;
        float v = j0 ? __fadd_rn(acc, g_O1[b][j0 - 1]) : acc;

        // index = cumsum - rn(k * pitch_row0[t])
        float index = __fsub_rn(v, __fmul_rn(k, pitch[t]));

        // exact trunc-remainder by 512 (bitwise == fmodf) + jnp.remainder fixup
        float q = truncf(__fmul_rn(index, 0.001953125f));
        float r = __fmaf_rn(-512.0f, q, index);
        if (r < 0.0f) r = __fadd_rn(r, 512.0f);
        if (__fsub_rn(512.0f, r) < 1e-5f) r = 0.0f;

        float lof   = floorf(r);
        float alpha = __fsub_rn(r, lof);
        int   ilo   = (int)lof;

        const int basei = b * L_DIM + t;
        const float2* ap = (const float2*)(att + (size_t)basei * N_WT);
        float2 a0 = ap[0], a1 = ap[1], a2 = ap[2], a3 = ap[3], a4 = ap[4];
        float aw[N_WT] = {a0.x, a0.y, a1.x, a1.y, a2.x,
                          a2.y, a3.x, a3.y, a4.x, a4.y};

        float acc2 = 0.0f;
        #pragma unroll
        for (int w = 0; w < N_WT; w++) {
            float2 pr = sp[w * WT_LEN + ilo];
            float wave = __fadd_rn(pr.x, __fmul_rn(alpha, __fsub_rn(pr.y, pr.x)));
            acc2 = __fadd_rn(acc2, __fmul_rn(wave, aw[w]));
        }
        out[basei] = __fmul_rn(acc2, env[basei]);
    }
}

// ---------------------------------------------------------------------------
// d_in order: 0 pitch, 1 envelope, 2 attention, 3 wavetables, 4 fir_h
// ---------------------------------------------------------------------------
extern "C" void kernel_launch(void* const* d_in, const int* in_sizes, int n_in,
                              void* d_out, int out_size)
{
    const float* pitch = (const float*)d_in[0];
    const float* env   = (const float*)d_in[1];
    const float* att   = (const float*)d_in[2];
    const float* wtab  = (const float*)d_in[3];
    const float* firh  = (const float*)d_in[4];
    float* out = (float*)d_out;

    cudaFuncSetAttribute(k_main, cudaFuncAttributeMaxDynamicSharedMemorySize,
                         SMEM_MAIN);

    k_s1<<<dim3(S1_TILES + N_WT, B_DIM), 256>>>(pitch, wtab, firh);
    k_scan<<<B_DIM, 1024>>>();
    k_main<<<dim3(L_DIM / TILE, B_DIM), TPB, SMEM_MAIN>>>(pitch, env, att, out);
}

// round 12
// speedup vs baseline: 1.4724x; 1.2036x over previous
#include <cuda_runtime.h>
#include <cstdint>

// Problem constants
#define B_DIM   16
#define L_DIM   160000
#define N_WT    10
#define WT_LEN  512
#define FIR_TAPS 31
#define WT_TOT  (N_WT * WT_LEN)

// Blocked-scan parameters (XLA ReduceWindowRewriter, base_length = 16)
#define NS1 10000
#define NS2 625
#define NS3 40
#define NS4 3

// k_main tiling: 640 threads x 5 samples = 3200-sample tiles, 50 tiles/row
#define TPB   640
#define SAMP  5
#define TILE  (TPB * SAMP)          // 3200

// k_s1 tiling: 20 tiles/row, 500 S1 groups per tile (512-thread blocks)
#define S1_TILES 20
#define S1_GRP   500

// k_main dynamic smem: transposed pair table + staged increments
#define SP_BYTES   (WT_LEN * 5 * 16)   // 40960 (512 x 5 float4)
#define SINC_BYTES (TILE * 4)          // 12800
#define SMEM_MAIN  (SP_BYTES + SINC_BYTES)   // 53760

__device__ __forceinline__ float KF() { return (float)(512.0 / 16000.0); }

// Scratch
__device__ float  g_S1[B_DIM][NS1];     // 16-block sums of increments
__device__ float  g_O1[B_DIM][NS1];     // composed inclusive scan at level 1
__device__ float4 g_wtp4t[WT_LEN * 5];  // transposed pairs: [i][j] = {lo2j,hi2j,lo2j+1,hi2j+1}

// ---------------------------------------------------------------------------
// k_s1: blocks x<20: S1 directly from 4x LDG.128 per 16-group (64B aligned),
// strict sequential rn adds in register order (verified bracketing).
// Blocks x in [20,25), y==0: FIR for wavetable rows (2j, 2j+1) + transposed
// pair writeout.
// ---------------------------------------------------------------------------
__global__ void __launch_bounds__(512) k_s1(
        const float* __restrict__ pitch,
        const float* __restrict__ wtab,
        const float* __restrict__ firh)
{
    __shared__ float srow[2][WT_LEN];
    __shared__ float sout[2][WT_LEN];
    __shared__ float sh[FIR_TAPS];

    const int tid = threadIdx.x;

    if (blockIdx.x >= S1_TILES) {               // FIR pair block
        if (blockIdx.y != 0) return;
        const int jj = blockIdx.x - S1_TILES;   // 0..4 -> rows 2jj, 2jj+1
        if (tid < FIR_TAPS) sh[tid] = firh[tid];
        if (tid < 512) {
            srow[0][tid] = wtab[(2 * jj    ) * WT_LEN + tid];
            srow[1][tid] = wtab[(2 * jj + 1) * WT_LEN + tid];
        }
        __syncthreads();
        // FIR: strict rn chain, ascending taps (verified bracketing)
        #pragma unroll
        for (int rr = 0; rr < 2; rr++) {
            float s = 0.0f;
            #pragma unroll
            for (int k = 0; k < FIR_TAPS; k++) {
                int j = (tid + k - 15 + WT_LEN) & 511;
                s = __fadd_rn(s, __fmul_rn(srow[rr][j], sh[k]));
            }
            sout[rr][tid] = s;
        }
        __syncthreads();
        // transposed pair writeout: tp[i*5 + jj]
        {
            int ip1 = (tid + 1) & 511;
            float4 v;
            v.x = sout[0][tid]; v.y = sout[0][ip1];
            v.z = sout[1][tid]; v.w = sout[1][ip1];
            g_wtp4t[tid * 5 + jj] = v;
        }
        return;
    }

    // S1 path: one 16-group per thread, 4x float4 direct loads
    const int j = blockIdx.x * S1_GRP + tid;
    if (tid >= S1_GRP) return;
    const int b = blockIdx.y;
    const float k = KF();
    const float4* P4 = (const float4*)(pitch + b * L_DIM + (j << 4));
    float4 v0 = P4[0], v1 = P4[1], v2 = P4[2], v3 = P4[3];

    float acc = 0.0f;
    acc = __fadd_rn(acc, __fmul_rn(k, v0.x));
    acc = __fadd_rn(acc, __fmul_rn(k, v0.y));
    acc = __fadd_rn(acc, __fmul_rn(k, v0.z));
    acc = __fadd_rn(acc, __fmul_rn(k, v0.w));
    acc = __fadd_rn(acc, __fmul_rn(k, v1.x));
    acc = __fadd_rn(acc, __fmul_rn(k, v1.y));
    acc = __fadd_rn(acc, __fmul_rn(k, v1.z));
    acc = __fadd_rn(acc, __fmul_rn(k, v1.w));
    acc = __fadd_rn(acc, __fmul_rn(k, v2.x));
    acc = __fadd_rn(acc, __fmul_rn(k, v2.y));
    acc = __fadd_rn(acc, __fmul_rn(k, v2.z));
    acc = __fadd_rn(acc, __fmul_rn(k, v2.w));
    acc = __fadd_rn(acc, __fmul_rn(k, v3.x));
    acc = __fadd_rn(acc, __fmul_rn(k, v3.y));
    acc = __fadd_rn(acc, __fmul_rn(k, v3.z));
    acc = __fadd_rn(acc, __fmul_rn(k, v3.w));
    g_S1[b][j] = acc;
}

// ---------------------------------------------------------------------------
// k_scan: one block per batch row.  Everything after S1 (verified chain):
//   stage S1 (pad-17) -> S2 -> S3 -> S4 -> O4 -> O3 -> O2 -> O1 -> writeout.
// ---------------------------------------------------------------------------
__global__ void k_scan()
{
    __shared__ float s1p[NS2 * 17];
    __shared__ float sS2[NS2];
    __shared__ float sS3[NS3];
    __shared__ float sS4[NS4];
    __shared__ float sO4[NS4];
    __shared__ float sO3[NS3];
    __shared__ float sO2[NS2];

    const int b   = blockIdx.x;
    const int tid = threadIdx.x;

    for (int i = tid; i < NS1; i += 1024)
        s1p[(i >> 4) * 17 + (i & 15)] = g_S1[b][i];
    __syncthreads();

    if (tid < NS2) {
        const float* row = s1p + tid * 17;
        float acc = 0.0f;
        #pragma unroll
        for (int e = 0; e < 16; e++)
            acc = __fadd_rn(acc, row[e]);
        sS2[tid] = acc;
    }
    __syncthreads();

    if (tid < NS3) {
        float acc = 0.0f;
        for (int e = 0; e < 16; e++) {
            int idx = (tid << 4) + e;
            if (idx < NS2) acc = __fadd_rn(acc, sS2[idx]);
        }
        sS3[tid] = acc;
    }
    __syncthreads();

    if (tid < NS4) {
        float acc = 0.0f;
        for (int e = 0; e < 16; e++) {
            int idx = (tid << 4) + e;
            if (idx < NS3) acc = __fadd_rn(acc, sS3[idx]);
        }
        sS4[tid] = acc;
    }
    __syncthreads();

    if (tid == 0) {
        float acc = 0.0f;
        for (int m = 0; m < NS4; m++) {
            acc = __fadd_rn(acc, sS4[m]);
            sO4[m] = acc;
        }
    }
    __syncthreads();

    if (tid < NS3) {
        int blk = tid >> 4;
        float acc = 0.0f;
        for (int m = (blk << 4); m <= tid; m++)
            acc = __fadd_rn(acc, sS3[m]);
        sO3[tid] = blk ? __fadd_rn(acc, sO4[blk - 1]) : acc;
    }
    __syncthreads();

    if (tid < NS2) {
        int blk = tid >> 4;
        float acc = 0.0f;
        for (int m = (blk << 4); m <= tid; m++)
            acc = __fadd_rn(acc, sS2[m]);
        sO2[tid] = blk ? __fadd_rn(acc, sO3[blk - 1]) : acc;
    }
    __syncthreads();

    if (tid < NS2) {
        float* row = s1p + tid * 17;
        float prev = (tid > 0) ? sO2[tid - 1] : 0.0f;
        float acc = 0.0f;
        #pragma unroll
        for (int e = 0; e < 16; e++) {
            acc = __fadd_rn(acc, row[e]);
            row[e] = (tid > 0) ? __fadd_rn(acc, prev) : acc;
        }
    }
    __syncthreads();

    for (int i = tid; i < NS1; i += 1024)
        g_O1[b][i] = s1p[(i >> 4) * 17 + (i & 15)];
}

// ---------------------------------------------------------------------------
// k_main: 3200-sample tiles, transposed pair table (5 x LDS.128 per sample).
// Per-sample arithmetic is the EXACT verified chain; dot order w-ascending.
// ---------------------------------------------------------------------------
__global__ void __launch_bounds__(TPB, 3) k_main(
        const float* __restrict__ pitch,
        const float* __restrict__ env,
        const float* __restrict__ att,
        float* __restrict__ out)
{
    extern __shared__ char smem_raw[];
    float4* sp4t = (float4*)smem_raw;                   // [512*5]
    float*  sinc = (float*)(smem_raw + SP_BYTES);

    const int tid = threadIdx.x;
    const int b   = blockIdx.y;
    const int base_t = blockIdx.x * TILE;
    const float k = KF();

    // pair-table fill: 4 x LDG.128 per thread (2560 float4)
    #pragma unroll
    for (int it = 0; it < (WT_LEN * 5) / TPB; it++)
        sp4t[tid + it * TPB] = g_wtp4t[tid + it * TPB];

    // staged increments (16-groups never straddle: 3200 % 16 == 0)
    #pragma unroll
    for (int s = 0; s < SAMP; s++) {
        int m = tid + s * TPB;
        sinc[m] = __fmul_rn(k, pitch[b * L_DIM + base_t + m]);
    }
    __syncthreads();

    #pragma unroll 1
    for (int s = 0; s < SAMP; s++) {
        const int m = tid + s * TPB;
        const int t = base_t + m;

        // strict sequential prefix within the 16-group
        const int r0 = m & 15;
        const int lb = m & ~15;
        float acc = 0.0f;
        for (int e = 0; e <= r0; e++)
            acc = __fadd_rn(acc, sinc[lb + e]);
        const int j0 = t >> 4;
        float v = j0 ? __fadd_rn(acc, g_O1[b][j0 - 1]) : acc;

        // index = cumsum - rn(k * pitch_row0[t])
        float index = __fsub_rn(v, __fmul_rn(k, pitch[t]));

        // exact trunc-remainder by 512 (bitwise == fmodf) + jnp.remainder fixup
        float q = truncf(__fmul_rn(index, 0.001953125f));
        float r = __fmaf_rn(-512.0f, q, index);
        if (r < 0.0f) r = __fadd_rn(r, 512.0f);
        if (__fsub_rn(512.0f, r) < 1e-5f) r = 0.0f;

        float lof   = floorf(r);
        float alpha = __fsub_rn(r, lof);
        int   ilo   = (int)lof;

        const int basei = b * L_DIM + t;
        const float2* ap = (const float2*)(att + (size_t)basei * N_WT);
        float2 a0 = ap[0], a1 = ap[1], a2 = ap[2], a3 = ap[3], a4 = ap[4];
        float aw[N_WT] = {a0.x, a0.y, a1.x, a1.y, a2.x,
                          a2.y, a3.x, a3.y, a4.x, a4.y};

        // 5 x LDS.128 from contiguous addresses; dot strict w-ascending
        const float4* tp = sp4t + ilo * 5;
        float acc2 = 0.0f;
        #pragma unroll
        for (int jj = 0; jj < 5; jj++) {
            float4 p = tp[jj];
            float wave0 = __fadd_rn(p.x, __fmul_rn(alpha, __fsub_rn(p.y, p.x)));
            acc2 = __fadd_rn(acc2, __fmul_rn(wave0, aw[2 * jj]));
            float wave1 = __fadd_rn(p.z, __fmul_rn(alpha, __fsub_rn(p.w, p.z)));
            acc2 = __fadd_rn(acc2, __fmul_rn(wave1, aw[2 * jj + 1]));
        }
        out[basei] = __fmul_rn(acc2, env[basei]);
    }
}

// ---------------------------------------------------------------------------
// d_in order: 0 pitch, 1 envelope, 2 attention, 3 wavetables, 4 fir_h
// ---------------------------------------------------------------------------
extern "C" void kernel_launch(void* const* d_in, const int* in_sizes, int n_in,
                              void* d_out, int out_size)
{
    const float* pitch = (const float*)d_in[0];
    const float* env   = (const float*)d_in[1];
    const float* att   = (const float*)d_in[2];
    const float* wtab  = (const float*)d_in[3];
    const float* firh  = (const float*)d_in[4];
    float* out = (float*)d_out;

    cudaFuncSetAttribute(k_main, cudaFuncAttributeMaxDynamicSharedMemorySize,
                         SMEM_MAIN);

    k_s1<<<dim3(S1_TILES + 5, B_DIM), 512>>>(pitch, wtab, firh);
    k_scan<<<B_DIM, 1024>>>();
    k_main<<<dim3(L_DIM / TILE, B_DIM), TPB, SMEM_MAIN>>>(pitch, env, att, out);
}

// round 13
// speedup vs baseline: 1.6110x; 1.0941x over previous
#include <cuda_runtime.h>
#include <cstdint>

// Problem constants
#define B_DIM   16
#define L_DIM   160000
#define N_WT    10
#define WT_LEN  512
#define FIR_TAPS 31
#define WT_TOT  (N_WT * WT_LEN)

// Blocked-scan parameters (XLA ReduceWindowRewriter, base_length = 16)
#define NS1 10000
#define NS2 625
#define NS3 40
#define NS4 3

// k_main tiling: 640 threads x 5 samples = 3200-sample tiles, 50 tiles/row
#define TPB   640
#define SAMP  5
#define TILE  (TPB * SAMP)          // 3200
#define NGRP  (TILE / 16)           // 200 16-groups per tile

// k_s1 tiling: 20 tiles/row, 500 S1 groups per tile (512-thread blocks)
#define S1_TILES 20
#define S1_GRP   500

// k_main dynamic smem: transposed pair table + finished cumsum values
#define SP_BYTES   (WT_LEN * 5 * 16)   // 40960 (512 x 5 float4)
#define SO0_BYTES  (TILE * 4)          // 12800
#define SMEM_MAIN  (SP_BYTES + SO0_BYTES)   // 53760

__device__ __forceinline__ float KF() { return (float)(512.0 / 16000.0); }

// Scratch
__device__ float  g_S1[B_DIM][NS1];     // 16-block sums of increments
__device__ float  g_O1[B_DIM][NS1];     // composed inclusive scan at level 1
__device__ float4 g_wtp4t[WT_LEN * 5];  // transposed pairs [i][j]={lo2j,hi2j,lo2j+1,hi2j+1}

// ---------------------------------------------------------------------------
// k_s1: blocks x<20: S1 directly from 4x LDG.128 per 16-group,
// strict sequential rn adds in register order (verified bracketing).
// Blocks x in [20,25), y==0: FIR for wavetable rows (2j, 2j+1) + transposed
// pair writeout.
// ---------------------------------------------------------------------------
__global__ void __launch_bounds__(512) k_s1(
        const float* __restrict__ pitch,
        const float* __restrict__ wtab,
        const float* __restrict__ firh)
{
    __shared__ float srow[2][WT_LEN];
    __shared__ float sout[2][WT_LEN];
    __shared__ float sh[FIR_TAPS];

    const int tid = threadIdx.x;

    if (blockIdx.x >= S1_TILES) {               // FIR pair block
        if (blockIdx.y != 0) return;
        const int jj = blockIdx.x - S1_TILES;   // 0..4 -> rows 2jj, 2jj+1
        if (tid < FIR_TAPS) sh[tid] = firh[tid];
        srow[0][tid] = wtab[(2 * jj    ) * WT_LEN + tid];
        srow[1][tid] = wtab[(2 * jj + 1) * WT_LEN + tid];
        __syncthreads();
        #pragma unroll
        for (int rr = 0; rr < 2; rr++) {
            float s = 0.0f;
            #pragma unroll
            for (int k = 0; k < FIR_TAPS; k++) {
                int j = (tid + k - 15 + WT_LEN) & 511;
                s = __fadd_rn(s, __fmul_rn(srow[rr][j], sh[k]));
            }
            sout[rr][tid] = s;
        }
        __syncthreads();
        {
            int ip1 = (tid + 1) & 511;
            float4 v;
            v.x = sout[0][tid]; v.y = sout[0][ip1];
            v.z = sout[1][tid]; v.w = sout[1][ip1];
            g_wtp4t[tid * 5 + jj] = v;
        }
        return;
    }

    // S1 path: one 16-group per thread, 4x float4 direct loads
    const int j = blockIdx.x * S1_GRP + tid;
    if (tid >= S1_GRP) return;
    const int b = blockIdx.y;
    const float k = KF();
    const float4* P4 = (const float4*)(pitch + b * L_DIM + (j << 4));
    float4 v0 = P4[0], v1 = P4[1], v2 = P4[2], v3 = P4[3];

    float acc = 0.0f;
    acc = __fadd_rn(acc, __fmul_rn(k, v0.x));
    acc = __fadd_rn(acc, __fmul_rn(k, v0.y));
    acc = __fadd_rn(acc, __fmul_rn(k, v0.z));
    acc = __fadd_rn(acc, __fmul_rn(k, v0.w));
    acc = __fadd_rn(acc, __fmul_rn(k, v1.x));
    acc = __fadd_rn(acc, __fmul_rn(k, v1.y));
    acc = __fadd_rn(acc, __fmul_rn(k, v1.z));
    acc = __fadd_rn(acc, __fmul_rn(k, v1.w));
    acc = __fadd_rn(acc, __fmul_rn(k, v2.x));
    acc = __fadd_rn(acc, __fmul_rn(k, v2.y));
    acc = __fadd_rn(acc, __fmul_rn(k, v2.z));
    acc = __fadd_rn(acc, __fmul_rn(k, v2.w));
    acc = __fadd_rn(acc, __fmul_rn(k, v3.x));
    acc = __fadd_rn(acc, __fmul_rn(k, v3.y));
    acc = __fadd_rn(acc, __fmul_rn(k, v3.z));
    acc = __fadd_rn(acc, __fmul_rn(k, v3.w));
    g_S1[b][j] = acc;
}

// ---------------------------------------------------------------------------
// k_scan: one block per batch row.  Everything after S1 (verified chain):
//   stage S1 (pad-17) -> S2 -> S3 -> S4 -> O4 -> O3 -> O2 -> O1 -> writeout.
// ---------------------------------------------------------------------------
__global__ void k_scan()
{
    __shared__ float s1p[NS2 * 17];
    __shared__ float sS2[NS2];
    __shared__ float sS3[NS3];
    __shared__ float sS4[NS4];
    __shared__ float sO4[NS4];
    __shared__ float sO3[NS3];
    __shared__ float sO2[NS2];

    const int b   = blockIdx.x;
    const int tid = threadIdx.x;

    for (int i = tid; i < NS1; i += 1024)
        s1p[(i >> 4) * 17 + (i & 15)] = g_S1[b][i];
    __syncthreads();

    if (tid < NS2) {
        const float* row = s1p + tid * 17;
        float acc = 0.0f;
        #pragma unroll
        for (int e = 0; e < 16; e++)
            acc = __fadd_rn(acc, row[e]);
        sS2[tid] = acc;
    }
    __syncthreads();

    if (tid < NS3) {
        float acc = 0.0f;
        for (int e = 0; e < 16; e++) {
            int idx = (tid << 4) + e;
            if (idx < NS2) acc = __fadd_rn(acc, sS2[idx]);
        }
        sS3[tid] = acc;
    }
    __syncthreads();

    if (tid < NS4) {
        float acc = 0.0f;
        for (int e = 0; e < 16; e++) {
            int idx = (tid << 4) + e;
            if (idx < NS3) acc = __fadd_rn(acc, sS3[idx]);
        }
        sS4[tid] = acc;
    }
    __syncthreads();

    if (tid == 0) {
        float acc = 0.0f;
        for (int m = 0; m < NS4; m++) {
            acc = __fadd_rn(acc, sS4[m]);
            sO4[m] = acc;
        }
    }
    __syncthreads();

    if (tid < NS3) {
        int blk = tid >> 4;
        float acc = 0.0f;
        for (int m = (blk << 4); m <= tid; m++)
            acc = __fadd_rn(acc, sS3[m]);
        sO3[tid] = blk ? __fadd_rn(acc, sO4[blk - 1]) : acc;
    }
    __syncthreads();

    if (tid < NS2) {
        int blk = tid >> 4;
        float acc = 0.0f;
        for (int m = (blk << 4); m <= tid; m++)
            acc = __fadd_rn(acc, sS2[m]);
        sO2[tid] = blk ? __fadd_rn(acc, sO3[blk - 1]) : acc;
    }
    __syncthreads();

    if (tid < NS2) {
        float* row = s1p + tid * 17;
        float prev = (tid > 0) ? sO2[tid - 1] : 0.0f;
        float acc = 0.0f;
        #pragma unroll
        for (int e = 0; e < 16; e++) {
            acc = __fadd_rn(acc, row[e]);
            row[e] = (tid > 0) ? __fadd_rn(acc, prev) : acc;
        }
    }
    __syncthreads();

    for (int i = tid; i < NS1; i += 1024)
        g_O1[b][i] = s1p[(i >> 4) * 17 + (i & 15)];
}

// ---------------------------------------------------------------------------
// k_main: O0 preamble (200 group-owner threads produce all 3200 finished
// cumsum values via the verified 16-add chains) + per-sample loop reduced to
// one LDS for the cumsum.  All arithmetic bitwise-identical to R12.
// ---------------------------------------------------------------------------
__global__ void __launch_bounds__(TPB, 3) k_main(
        const float* __restrict__ pitch,
        const float* __restrict__ env,
        const float* __restrict__ att,
        float* __restrict__ out)
{
    extern __shared__ char smem_raw[];
    float4* sp4t = (float4*)smem_raw;                   // [512*5]
    float*  so0  = (float*)(smem_raw + SP_BYTES);       // [3200] finished cumsums

    const int tid = threadIdx.x;
    const int b   = blockIdx.y;
    const int base_t = blockIdx.x * TILE;
    const float k = KF();

    // pair-table fill: 4 x LDG.128 per thread (2560 float4)
    #pragma unroll
    for (int it = 0; it < (WT_LEN * 5) / TPB; it++)
        sp4t[tid + it * TPB] = g_wtp4t[tid + it * TPB];

    // O0 preamble: threads 0..199 each own one 16-group
    if (tid < NGRP) {
        const int gj = (base_t >> 4) + tid;             // global group id
        const float4* P4 = (const float4*)(pitch + b * L_DIM + base_t + (tid << 4));
        float4 v0 = P4[0], v1 = P4[1], v2 = P4[2], v3 = P4[3];
        const float vals[16] = {v0.x, v0.y, v0.z, v0.w, v1.x, v1.y, v1.z, v1.w,
                                v2.x, v2.y, v2.z, v2.w, v3.x, v3.y, v3.z, v3.w};
        const bool  has_prev = (gj > 0);
        const float o1p = has_prev ? g_O1[b][gj - 1] : 0.0f;
        float* dst = so0 + (tid << 4);
        float acc = 0.0f;
        #pragma unroll
        for (int e = 0; e < 16; e++) {
            acc = __fadd_rn(acc, __fmul_rn(k, vals[e]));
            dst[e] = has_prev ? __fadd_rn(acc, o1p) : acc;
        }
    }
    __syncthreads();

    #pragma unroll 1
    for (int s = 0; s < SAMP; s++) {
        const int m = tid + s * TPB;
        const int t = base_t + m;

        // finished cumsum (bitwise == verified chain)
        float v = so0[m];

        // index = cumsum - rn(k * pitch_row0[t])
        float index = __fsub_rn(v, __fmul_rn(k, pitch[t]));

        // exact trunc-remainder by 512 (bitwise == fmodf) + jnp.remainder fixup
        float q = truncf(__fmul_rn(index, 0.001953125f));
        float r = __fmaf_rn(-512.0f, q, index);
        if (r < 0.0f) r = __fadd_rn(r, 512.0f);
        if (__fsub_rn(512.0f, r) < 1e-5f) r = 0.0f;

        float lof   = floorf(r);
        float alpha = __fsub_rn(r, lof);
        int   ilo   = (int)lof;

        const int basei = b * L_DIM + t;
        const float2* ap = (const float2*)(att + (size_t)basei * N_WT);
        float2 a0 = ap[0], a1 = ap[1], a2 = ap[2], a3 = ap[3], a4 = ap[4];
        float aw[N_WT] = {a0.x, a0.y, a1.x, a1.y, a2.x,
                          a2.y, a3.x, a3.y, a4.x, a4.y};

        // 5 x LDS.128 from contiguous addresses; dot strict w-ascending
        const float4* tp = sp4t + ilo * 5;
        float acc2 = 0.0f;
        #pragma unroll
        for (int jj = 0; jj < 5; jj++) {
            float4 p = tp[jj];
            float wave0 = __fadd_rn(p.x, __fmul_rn(alpha, __fsub_rn(p.y, p.x)));
            acc2 = __fadd_rn(acc2, __fmul_rn(wave0, aw[2 * jj]));
            float wave1 = __fadd_rn(p.z, __fmul_rn(alpha, __fsub_rn(p.w, p.z)));
            acc2 = __fadd_rn(acc2, __fmul_rn(wave1, aw[2 * jj + 1]));
        }
        out[basei] = __fmul_rn(acc2, env[basei]);
    }
}

// ---------------------------------------------------------------------------
// d_in order: 0 pitch, 1 envelope, 2 attention, 3 wavetables, 4 fir_h
// ---------------------------------------------------------------------------
extern "C" void kernel_launch(void* const* d_in, const int* in_sizes, int n_in,
                              void* d_out, int out_size)
{
    const float* pitch = (const float*)d_in[0];
    const float* env   = (const float*)d_in[1];
    const float* att   = (const float*)d_in[2];
    const float* wtab  = (const float*)d_in[3];
    const float* firh  = (const float*)d_in[4];
    float* out = (float*)d_out;

    cudaFuncSetAttribute(k_main, cudaFuncAttributeMaxDynamicSharedMemorySize,
                         SMEM_MAIN);

    k_s1<<<dim3(S1_TILES + 5, B_DIM), 512>>>(pitch, wtab, firh);
    k_scan<<<B_DIM, 1024>>>();
    k_main<<<dim3(L_DIM / TILE, B_DIM), TPB, SMEM_MAIN>>>(pitch, env, att, out);
}